// round 10
// baseline (speedup 1.0000x reference)
#include <cuda_runtime.h>
#include <math.h>

// ACT_R activation recurrence — wavefront column sweep + named-barrier parking.
// sp: [S=512, B=256, 1] f32 (sorted along S).  w: [a, c, s, tau, h].
// out: [S-1, B, 1] f32.
//
//   E_i = sum_{j<i} max(sc_i - sc_j, 1)^{p_j},  p_j = -(c*E_j + a),  E_0 = 0
//   out[i-1] = sigmoid((log(E_i) - tau)/s)
//
// One block per batch element (grid=256), one thread per row (block=512),
// natural warp order (hi-wid = latest = critical path gets arbiter priority).
//
// Synchronization redesign vs R7: far consumers no longer poll. Producer
// warp m, after publishing its 32 diagonal p-columns, does
// bar.arrive(m+1, 32*(15-m)); consumer warps w >= m+2 do bar.sync before
// consuming block m with plain vectorized loads. Barrier-parked warps burn
// ZERO issue slots (vs ~5 instr per 64cyc per polling warp before — which
// consumed over half the SM's issue bandwidth). Only the immediate successor
// warp (w = m+1) keeps the eager NaN-sentinel hot-spin path so the serial
// diagonal handoff stays low-latency.

#define S_LEN 512
#define BATCH 256

__device__ __forceinline__ float ex2f(float x) {
    float y; asm("ex2.approx.ftz.f32 %0, %1;" : "=f"(y) : "f"(x)); return y;
}
__device__ __forceinline__ float lg2f(float x) {
    float y; asm("lg2.approx.ftz.f32 %0, %1;" : "=f"(y) : "f"(x)); return y;
}
__device__ __forceinline__ void bar_arrive(int id, int cnt) {
    asm volatile("bar.arrive %0, %1;" :: "r"(id), "r"(cnt) : "memory");
}
__device__ __forceinline__ void bar_sync_named(int id, int cnt) {
    asm volatile("bar.sync %0, %1;" :: "r"(id), "r"(cnt) : "memory");
}

__global__ void __launch_bounds__(S_LEN, 2)
actr_kernel(const float* __restrict__ sp, const float* __restrict__ w,
            float* __restrict__ out) {
    __shared__ __align__(16) float sc[S_LEN];   // scaled timestamps
    __shared__ __align__(16) float psm[S_LEN];  // published p_j (NaN = not ready)

    const int b    = blockIdx.x;
    const int t    = threadIdx.x;          // owned row (natural order)
    const int lane = t & 31;
    const int wid  = t >> 5;
    const int base = wid * 32;

    const float a = w[0], c = w[1], s = w[2], tau = w[3], h = w[4];
    const float scale = 86400.0f * h;

    const float my_sc = sp[t * BATCH + b] * scale;
    sc[t]  = my_sc;
    psm[t] = __int_as_float(0x7fc00000);   // NaN sentinel
    __syncthreads();

    volatile float* vp = psm;
    float accA = 0.f, accB = 0.f;          // dual accumulators for FADD ILP

    // ---- far blocks m = 0 .. wid-2: barrier-gated, zero-cost waiting ----
    for (int m = 0; m <= wid - 2; ++m) {
        bar_sync_named(m + 1, 32 * (15 - m));      // block m fully published
        const int j0 = m * 32;
        #pragma unroll
        for (int jj = 0; jj < 32; jj += 4) {
            const float4 s4 = *reinterpret_cast<const float4*>(&sc[j0 + jj]);
            float l0 = lg2f(fmaxf(my_sc - s4.x, 1.f));
            float l1 = lg2f(fmaxf(my_sc - s4.y, 1.f));
            float l2 = lg2f(fmaxf(my_sc - s4.z, 1.f));
            float l3 = lg2f(fmaxf(my_sc - s4.w, 1.f));
            const float4 p4 = *reinterpret_cast<const float4*>(&psm[j0 + jj]);
            accA += ex2f(p4.x * l0);  accB += ex2f(p4.y * l1);
            accA += ex2f(p4.z * l2);  accB += ex2f(p4.w * l3);
        }
    }

    // ---- immediate predecessor block: eager hot-spin, track the wavefront ----
    if (wid >= 1) {
        const int j0 = base - 32;
        for (int jj = 0; jj < 32; ++jj) {
            const int j = j0 + jj;
            float l  = lg2f(fmaxf(my_sc - sc[j], 1.f));   // off-chain, pre-spin
            float pj = vp[j];
            while (__isnanf(pj)) { pj = vp[j]; }          // ~1 warp/CTA spins
            if (jj & 1) accB += ex2f(pj * l);
            else        accA += ex2f(pj * l);
        }
    }
    float acc = accA + accB;

    // ---- diagonal block: serial chain via shfl (R7 FFMA-shortened step) ----
    // q = -(c*acc + a) over columns accumulated so far (off-chain).
    // Lane k+1's publish value: p = q_prev + (-c)*term_k (one FFMA on chain).
    const float negc = -c;
    float q = -fmaf(c, acc, a);            // valid p for lane 0 (cols < base)
    float p_mine = q;
    #pragma unroll 1
    for (int k = 0; k < 31; ++k) {
        float l = lg2f(fmaxf(my_sc - sc[base + k], 1.f));  // off-chain
        if (lane == k) vp[base + k] = p_mine;  // publish for eager successor
        float pj = __shfl_sync(0xffffffffu, p_mine, k);
        float term = ex2f(pj * l);
        if (lane == k + 1) p_mine = fmaf(negc, term, q);   // fast-path publish
        if (lane > k) {
            acc += term;                   // off-chain bookkeeping
            q = -fmaf(c, acc, a);          // q for this lane's later fast-path
        }
    }
    if (lane == 31) vp[base + 31] = p_mine;   // last column of the block

    // ---- producer signal: block fully published -> release parked warps ----
    if (wid <= 13) bar_arrive(wid + 1, 32 * (15 - wid));
    // (block 14's only consumer is warp 15's eager path; block 15 has none)

    // ---- epilogue: sigmoid((m - tau)/s), m = log(E) ----
    if (t >= 1) {
        const float LN2 = 0.69314718055994530942f;
        const float inv_sln2 = 1.0f / (s * LN2);
        float m = lg2f(acc) * LN2;
        float e = ex2f((tau - m) * inv_sln2);
        out[(t - 1) * BATCH + b] = __fdividef(1.f, 1.f + e);
    }
}

extern "C" void kernel_launch(void* const* d_in, const int* in_sizes, int n_in,
                              void* d_out, int out_size) {
    const float* sp = (const float*)d_in[0];
    const float* w  = (const float*)d_in[1];
    float* out      = (float*)d_out;
    (void)in_sizes; (void)n_in; (void)out_size;
    actr_kernel<<<BATCH, S_LEN>>>(sp, w, out);
}

// round 12
// speedup vs baseline: 1.1243x; 1.1243x over previous
#include <cuda_runtime.h>
#include <math.h>

// ACT_R activation recurrence — wavefront column sweep (R7 structure) +
// FMA-pipe polynomial exp2 offload for 3/4 of far-loop terms.
// sp: [S=512, B=256, 1] f32 (sorted along S).  w: [a, c, s, tau, h].
// out: [S-1, B, 1] f32.
//
//   E_i = sum_{j<i} max(sc_i - sc_j, 1)^{p_j},  p_j = -(c*E_j + a),  E_0 = 0
//   out[i-1] = sigmoid((log(E_i) - tau)/s)
//
// One block per batch element (grid=256), one thread per row (block=512),
// natural warp order. p_j published via NaN-sentinel smem; group-of-4 poll.
// MUFU and FMA pipes are balanced: lg2 (all terms) + 1/4 of far ex2 + all
// chain-critical ex2 on MUFU (~21K cyc/SMSP); 3/4 of far ex2 as 5th-order
// FFMA polynomial on the otherwise-idle FMA pipe (~20K cyc/SMSP).

#define S_LEN 512
#define BATCH 256

__device__ __forceinline__ float ex2f(float x) {
    float y; asm("ex2.approx.ftz.f32 %0, %1;" : "=f"(y) : "f"(x)); return y;
}
__device__ __forceinline__ float lg2f(float x) {
    float y; asm("lg2.approx.ftz.f32 %0, %1;" : "=f"(y) : "f"(x)); return y;
}
__device__ __forceinline__ float4 lds_v4_vol(const float* p) {
    float4 v; unsigned a = (unsigned)__cvta_generic_to_shared(p);
    asm volatile("ld.volatile.shared.v4.f32 {%0,%1,%2,%3}, [%4];"
                 : "=f"(v.x), "=f"(v.y), "=f"(v.z), "=f"(v.w) : "r"(a));
    return v;
}

// exp2(x) for x <= 0 on the FMA/ALU pipes (no MUFU). ~2e-6 rel err.
// Magic-number round-to-nearest range reduction, r in [-0.5, 0.5],
// degree-5 Taylor/minimax, scale via exponent-bit construction.
__device__ __forceinline__ float exp2_poly(float x) {
    x = fmaxf(x, -120.0f);                     // keep scale construction valid
    float t  = x + 12582912.0f;                // 1.5*2^23: RN-int in mantissa
    int   i  = __float_as_int(t);
    float xf = t - 12582912.0f;                // nearest integer to x
    float r  = x - xf;                         // [-0.5, 0.5]
    float sc = __int_as_float((i - 0x4B3FFF81) << 23);   // 2^round(x)
    float p  =          1.33335581e-3f;
    p = fmaf(p, r, 9.61812911e-3f);
    p = fmaf(p, r, 5.55041087e-2f);
    p = fmaf(p, r, 2.40226507e-1f);
    p = fmaf(p, r, 6.93147182e-1f);
    p = fmaf(p, r, 1.0f);
    return p * sc;
}

__global__ void __launch_bounds__(S_LEN, 2)
actr_kernel(const float* __restrict__ sp, const float* __restrict__ w,
            float* __restrict__ out) {
    __shared__ __align__(16) float sc[S_LEN];   // scaled timestamps
    __shared__ __align__(16) float psm[S_LEN];  // published p_j (NaN = not ready)

    const int b    = blockIdx.x;
    const int t    = threadIdx.x;          // owned row (natural order)
    const int lane = t & 31;
    const int base = t & ~31;              // this warp's diagonal base row

    const float a = w[0], c = w[1], s = w[2], tau = w[3], h = w[4];
    const float scale = 86400.0f * h;

    const float my_sc = sp[t * BATCH + b] * scale;
    sc[t]  = my_sc;
    psm[t] = __int_as_float(0x7fc00000);   // NaN sentinel
    __syncthreads();

    volatile float* vp = psm;
    float accA = 0.f, accB = 0.f;          // dual accumulators for FADD ILP

    // ---- off-diagonal columns j = 0 .. base-1, groups of 4 ----
    for (int j = 0; j < base; j += 4) {
        // lg2s depend only on timestamps: issue BEFORE the poll to fill waits
        const float4 s4 = *reinterpret_cast<const float4*>(&sc[j]);
        float l0 = lg2f(fmaxf(my_sc - s4.x, 1.f));
        float l1 = lg2f(fmaxf(my_sc - s4.y, 1.f));
        float l2 = lg2f(fmaxf(my_sc - s4.z, 1.f));
        float l3 = lg2f(fmaxf(my_sc - s4.w, 1.f));
        // publishes are strictly in column order: once j+3 is ready, all are
        float p3 = vp[j + 3];
        while (__isnanf(p3)) { __nanosleep(40); p3 = vp[j + 3]; }
        asm volatile("" ::: "memory");     // keep group read below the poll
        float4 p4 = lds_v4_vol(&psm[j]);
        // pipe balance: 3 poly-exp2 (FMA pipe) + 1 MUFU ex2 per group
        accA += exp2_poly(p4.x * l0);
        accB += exp2_poly(p4.y * l1);
        accA += exp2_poly(p4.z * l2);
        accB += ex2f(p4.w * l3);
    }
    float acc = accA + accB;

    // ---- diagonal block: serial chain via shfl (FFMA-shortened step) ----
    // q = -(c*acc + a) over columns accumulated so far (off-chain).
    // Lane k+1's publish value: p = q_prev + (-c)*term_k (one FFMA on chain).
    const float negc = -c;
    float q = -fmaf(c, acc, a);            // valid p for lane 0 (cols < base)
    float p_mine = q;
    #pragma unroll 1
    for (int k = 0; k < 31; ++k) {
        float l = lg2f(fmaxf(my_sc - sc[base + k], 1.f));  // off-chain
        if (lane == k) vp[base + k] = p_mine;  // publish for successor warps
        float pj = __shfl_sync(0xffffffffu, p_mine, k);
        float term = ex2f(pj * l);             // latency-critical: keep MUFU
        if (lane == k + 1) p_mine = fmaf(negc, term, q);   // fast-path publish
        if (lane > k) {
            acc += term;                   // off-chain bookkeeping
            q = -fmaf(c, acc, a);          // q for this lane's later fast-path
        }
    }
    if (lane == 31) vp[base + 31] = p_mine;   // last column for successor warps

    // ---- epilogue: sigmoid((m - tau)/s), m = log(E) ----
    if (t >= 1) {
        const float LN2 = 0.69314718055994530942f;
        const float inv_sln2 = 1.0f / (s * LN2);
        float m = lg2f(acc) * LN2;
        float e = ex2f((tau - m) * inv_sln2);
        out[(t - 1) * BATCH + b] = __fdividef(1.f, 1.f + e);
    }
}

extern "C" void kernel_launch(void* const* d_in, const int* in_sizes, int n_in,
                              void* d_out, int out_size) {
    const float* sp = (const float*)d_in[0];
    const float* w  = (const float*)d_in[1];
    float* out      = (float*)d_out;
    (void)in_sizes; (void)n_in; (void)out_size;
    actr_kernel<<<BATCH, S_LEN>>>(sp, w, out);
}

// round 13
// speedup vs baseline: 1.2218x; 1.0867x over previous
#include <cuda_runtime.h>
#include <math.h>

// ACT_R activation recurrence — wavefront column sweep (R7 structure).
// sp: [S=512, B=256, 1] f32 (sorted along S).  w: [a, c, s, tau, h].
// out: [S-1, B, 1] f32.
//
//   E_i = sum_{j<i} max(sc_i - sc_j, 1)^{p_j},  p_j = -(c*E_j + a),  E_0 = 0
//   out[i-1] = sigmoid((log(E_i) - tau)/s)
//
// One block per batch element (grid=256), one thread per row (block=512),
// natural warp order. Consumers (far loop) keep MUFU lg2/ex2 — throughput-
// optimal. The DIAGONAL chain's exp2 runs as an FFMA polynomial on the
// lightly-loaded FMA pipe, bypassing the persistently-oversubscribed MUFU
// queue that was adding ~60 cyc of queue delay to each of the 512
// chain-critical steps. Diagonal lg2 is software-pipelined one iteration
// ahead so MUFU queueing never lands on the chain.

#define S_LEN 512
#define BATCH 256

__device__ __forceinline__ float ex2f(float x) {
    float y; asm("ex2.approx.ftz.f32 %0, %1;" : "=f"(y) : "f"(x)); return y;
}
__device__ __forceinline__ float lg2f(float x) {
    float y; asm("lg2.approx.ftz.f32 %0, %1;" : "=f"(y) : "f"(x)); return y;
}
__device__ __forceinline__ float4 lds_v4_vol(const float* p) {
    float4 v; unsigned a = (unsigned)__cvta_generic_to_shared(p);
    asm volatile("ld.volatile.shared.v4.f32 {%0,%1,%2,%3}, [%4];"
                 : "=f"(v.x), "=f"(v.y), "=f"(v.z), "=f"(v.w) : "r"(a));
    return v;
}

// exp2(x) for x <= 0 on the FMA/ALU pipes (no MUFU). ~2e-6 rel err.
// Magic-number round-to-nearest range reduction, r in [-0.5, 0.5],
// degree-5 minimax, scale via exponent-bit construction.
__device__ __forceinline__ float exp2_poly(float x) {
    x = fmaxf(x, -120.0f);                     // keep scale construction valid
    float t  = x + 12582912.0f;                // 1.5*2^23: RN-int in mantissa
    int   i  = __float_as_int(t);
    float xf = t - 12582912.0f;                // nearest integer to x
    float r  = x - xf;                         // [-0.5, 0.5]
    float sc = __int_as_float((i - 0x4B3FFF81) << 23);   // 2^round(x)
    float p  =          1.33335581e-3f;
    p = fmaf(p, r, 9.61812911e-3f);
    p = fmaf(p, r, 5.55041087e-2f);
    p = fmaf(p, r, 2.40226507e-1f);
    p = fmaf(p, r, 6.93147182e-1f);
    p = fmaf(p, r, 1.0f);
    return p * sc;
}

__global__ void __launch_bounds__(S_LEN, 2)
actr_kernel(const float* __restrict__ sp, const float* __restrict__ w,
            float* __restrict__ out) {
    __shared__ __align__(16) float sc[S_LEN];   // scaled timestamps
    __shared__ __align__(16) float psm[S_LEN];  // published p_j (NaN = not ready)

    const int b    = blockIdx.x;
    const int t    = threadIdx.x;          // owned row (natural order)
    const int lane = t & 31;
    const int base = t & ~31;              // this warp's diagonal base row

    const float a = w[0], c = w[1], s = w[2], tau = w[3], h = w[4];
    const float scale = 86400.0f * h;

    const float my_sc = sp[t * BATCH + b] * scale;
    sc[t]  = my_sc;
    psm[t] = __int_as_float(0x7fc00000);   // NaN sentinel
    __syncthreads();

    volatile float* vp = psm;
    float accA = 0.f, accB = 0.f;          // dual accumulators for FADD ILP

    // ---- off-diagonal columns j = 0 .. base-1, groups of 4 (all MUFU) ----
    for (int j = 0; j < base; j += 4) {
        // lg2s depend only on timestamps: issue BEFORE the poll to fill waits
        const float4 s4 = *reinterpret_cast<const float4*>(&sc[j]);
        float l0 = lg2f(fmaxf(my_sc - s4.x, 1.f));
        float l1 = lg2f(fmaxf(my_sc - s4.y, 1.f));
        float l2 = lg2f(fmaxf(my_sc - s4.z, 1.f));
        float l3 = lg2f(fmaxf(my_sc - s4.w, 1.f));
        // publishes are strictly in column order: once j+3 is ready, all are
        float p3 = vp[j + 3];
        while (__isnanf(p3)) { __nanosleep(40); p3 = vp[j + 3]; }
        asm volatile("" ::: "memory");     // keep group read below the poll
        float4 p4 = lds_v4_vol(&psm[j]);
        accA += ex2f(p4.x * l0);  accB += ex2f(p4.y * l1);
        accA += ex2f(p4.z * l2);  accB += ex2f(p4.w * l3);
    }
    float acc = accA + accB;

    // ---- diagonal block: serial chain via shfl; exp2 on the FMA pipe ----
    // q = -(c*acc + a) over columns accumulated so far (off-chain).
    // Lane k+1's publish value: p = q_prev + (-c)*term_k (one FFMA on chain).
    const float negc = -c;
    float q = -fmaf(c, acc, a);            // valid p for lane 0 (cols < base)
    float p_mine = q;
    float l_cur = lg2f(fmaxf(my_sc - sc[base], 1.f));
    #pragma unroll 1
    for (int k = 0; k < 31; ++k) {
        // prefetch next column's lg2 one iteration early (off the chain even
        // if the MUFU queue is deep)
        float l_next = lg2f(fmaxf(my_sc - sc[base + k + 1], 1.f));
        if (lane == k) vp[base + k] = p_mine;  // publish for successor warps
        float pj = __shfl_sync(0xffffffffu, p_mine, k);
        float term = exp2_poly(pj * l_cur);    // FMA pipe: no MUFU queue toll
        if (lane == k + 1) p_mine = fmaf(negc, term, q);   // fast-path publish
        if (lane > k) {
            acc += term;                   // off-chain bookkeeping
            q = -fmaf(c, acc, a);          // q for this lane's later fast-path
        }
        l_cur = l_next;
    }
    if (lane == 31) vp[base + 31] = p_mine;   // last column for successor warps

    // ---- epilogue: sigmoid((m - tau)/s), m = log(E) ----
    if (t >= 1) {
        const float LN2 = 0.69314718055994530942f;
        const float inv_sln2 = 1.0f / (s * LN2);
        float m = lg2f(acc) * LN2;
        float e = ex2f((tau - m) * inv_sln2);
        out[(t - 1) * BATCH + b] = __fdividef(1.f, 1.f + e);
    }
}

extern "C" void kernel_launch(void* const* d_in, const int* in_sizes, int n_in,
                              void* d_out, int out_size) {
    const float* sp = (const float*)d_in[0];
    const float* w  = (const float*)d_in[1];
    float* out      = (float*)d_out;
    (void)in_sizes; (void)n_in; (void)out_size;
    actr_kernel<<<BATCH, S_LEN>>>(sp, w, out);
}